// round 14
// baseline (speedup 1.0000x reference)
#include <cuda_runtime.h>
#include <cstdint>

#define HH 128
#define WW 128
#define BB 8
#define NCH 32            // 32 k-chunks; chunk = 8 input channels x 4 branches = 32 y-channels
#define NSTG 3            // A/Y/X pipeline stages

// ---- smem byte layout (per CTA) ----
#define AB_OFF 0                      // 3 x 36864 : A stage [256 m][36 w] (stride 144B)
#define AB_SZ  36864
#define YB_OFF 110592                 // 3 x 8704  : Y stage [32 k][68 w] (stride 272B)
#define YB_SZ  8704
#define XB_OFF 136704                 // 3 x 20736 : X stage [8 ch][9 rows][72 px] fp32
#define XB_SZ  20736
#define SMEM_BYTES 198912

// named barrier ids
#define BFULL(s)  (1 + (s))
#define BEMPTY(s) (4 + (s))
#define BPROD     7

// wproj pre-converted to tf32: [chunk(32)][m(256)][k(32)] u32
__device__ uint32_t g_A_tf32[32 * 256 * 32];
// depthwise weights packed: [ch(256)][conv(4: h1,h2,v1,v2)][12 floats (9 + pad)]
__device__ float g_dw[256 * 4 * 12];

// ================= helpers =================
__device__ __forceinline__ uint32_t smem_u32(const void* p) {
    uint32_t a;
    asm("{ .reg .u64 t; cvta.to.shared.u64 t, %1; cvt.u32.u64 %0, t; }" : "=r"(a) : "l"(p));
    return a;
}
__device__ __forceinline__ void cpa16(uint32_t dst, const void* src) {
    unsigned long long g = (unsigned long long)__cvta_generic_to_global((void*)src);
    asm volatile("cp.async.cg.shared.global [%0], [%1], 16;" :: "r"(dst), "l"(g));
}
__device__ __forceinline__ void cpa16z(uint32_t dst, const void* src, int sz) {
    unsigned long long g = (unsigned long long)__cvta_generic_to_global((void*)src);
    asm volatile("cp.async.cg.shared.global [%0], [%1], 16, %2;" :: "r"(dst), "l"(g), "r"(sz));
}
__device__ __forceinline__ uint32_t f2tf32(float v) {
    uint32_t u;
    asm("cvt.rna.tf32.f32 %0, %1;" : "=r"(u) : "f"(v));
    return u;
}
__device__ __forceinline__ void ldsm4(uint32_t* r, uint32_t addr) {
    asm volatile("ldmatrix.sync.aligned.m8n8.x4.shared.b16 {%0,%1,%2,%3}, [%4];"
        : "=r"(r[0]), "=r"(r[1]), "=r"(r[2]), "=r"(r[3]) : "r"(addr));
}
__device__ __forceinline__ void mma_tf32(float* d, const uint32_t* a, const uint32_t* b) {
    asm volatile("mma.sync.aligned.m16n8k8.row.col.f32.tf32.tf32.f32 "
        "{%0,%1,%2,%3}, {%4,%5,%6,%7}, {%8,%9}, {%0,%1,%2,%3};"
        : "+f"(d[0]), "+f"(d[1]), "+f"(d[2]), "+f"(d[3])
        : "r"(a[0]), "r"(a[1]), "r"(a[2]), "r"(a[3]), "r"(b[0]), "r"(b[1]));
}
__device__ __forceinline__ void bar_sync(int id) {
    asm volatile("bar.sync %0, 384;" :: "r"(id) : "memory");
}
__device__ __forceinline__ void bar_arrive(int id) {
    asm volatile("bar.arrive %0, 384;" :: "r"(id) : "memory");
}
__device__ __forceinline__ void bar_prod() {
    asm volatile("bar.sync %0, 128;" :: "r"(BPROD) : "memory");
}

// ================= prep: wproj -> tf32, dw weights -> packed =================
__global__ void se_prep(const float* __restrict__ wproj,
                        const float* __restrict__ wh1, const float* __restrict__ wh2,
                        const float* __restrict__ wv1, const float* __restrict__ wv2)
{
    int idx = blockIdx.x * 256 + threadIdx.x;   // 262144
    int k = idx & 31;
    int m = (idx >> 5) & 255;
    int c = idx >> 13;
    int br = k >> 3, lc = k & 7;
    float v = wproj[m * 1024 + br * 256 + c * 8 + lc];
    g_A_tf32[(c * 256 + m) * 32 + k] = f2tf32(v);

    if (blockIdx.x == 0) {
        for (int i = threadIdx.x; i < 9216; i += 256) {
            int ch = i / 36, r = i - ch * 36;
            int conv = r / 9, kk = r - conv * 9;
            const float* p = (conv == 0) ? wh1 : (conv == 1) ? wh2 : (conv == 2) ? wv1 : wv2;
            g_dw[(ch * 4 + conv) * 12 + kk] = p[ch * 9 + kk];
        }
    }
}

// ================= main: warp-specialized, fully-async producer =================
// grid (2, HH, BB): blockIdx.x = half (N-half of the row)
__global__ __launch_bounds__(384, 1)
void se_main(const float* __restrict__ x, float* __restrict__ out)
{
    extern __shared__ char smc[];
    const uint32_t sb = smem_u32(smc);
    const int half = blockIdx.x, h = blockIdx.y, b = blockIdx.z;
    const int t = threadIdx.x, lane = t & 31;

    const float* xb = x + (long)b * 256 * HH * WW;

    if (t < 256) {
        // ================== CONSUMERS: 8 warps, MMA only ==================
        const int wid = t >> 5;
        const int wm = (wid & 3) * 64;       // M tile base
        const int wn = (wid >> 2) * 32;      // N tile base within 64-px half
        const int fr = lane >> 2, fq = lane & 3;
        const uint32_t aLane = (uint32_t)(((lane & 7) + ((lane >> 3) & 1) * 8) * 144 + ((lane >> 4) << 4));

        float acc[4][4][4];
        #pragma unroll
        for (int i = 0; i < 4; ++i)
            #pragma unroll
            for (int j = 0; j < 4; ++j)
                #pragma unroll
                for (int e = 0; e < 4; ++e) acc[i][j][e] = 0.f;

        uint32_t a[2][4][4];
        uint32_t bf[2][4][2];

        for (int c = 0; c < NCH; ++c) {
            const int s = c % NSTG;
            bar_sync(BFULL(s));

            const uint32_t abase = sb + AB_OFF + (uint32_t)(s * AB_SZ) + (uint32_t)(wm * 144) + aLane;
            const uint32_t* Yp = (const uint32_t*)(smc + YB_OFF + s * YB_SZ);

            #pragma unroll
            for (int mt = 0; mt < 4; ++mt)
                ldsm4(a[0][mt], abase + (uint32_t)(mt * 16 * 144));
            #pragma unroll
            for (int nt = 0; nt < 4; ++nt) {
                const int col = wn + nt * 8 + fr;
                bf[0][nt][0] = Yp[fq * 68 + col];
                bf[0][nt][1] = Yp[(fq + 4) * 68 + col];
            }

            #pragma unroll
            for (int ks = 0; ks < 4; ++ks) {
                const int cur = ks & 1, nxt = cur ^ 1;
                if (ks < 3) {
                    const int k0 = (ks + 1) * 8;
                    #pragma unroll
                    for (int mt = 0; mt < 4; ++mt)
                        ldsm4(a[nxt][mt], abase + (uint32_t)(mt * 16 * 144 + k0 * 4));
                    #pragma unroll
                    for (int nt = 0; nt < 4; ++nt) {
                        const int col = wn + nt * 8 + fr;
                        bf[nxt][nt][0] = Yp[(k0 + fq) * 68 + col];
                        bf[nxt][nt][1] = Yp[(k0 + fq + 4) * 68 + col];
                    }
                    if (ks == 2 && c + NSTG < NCH) bar_arrive(BEMPTY(s));
                }
                #pragma unroll
                for (int mt = 0; mt < 4; ++mt)
                    #pragma unroll
                    for (int nt = 0; nt < 4; ++nt)
                        mma_tf32(acc[mt][nt], a[cur][mt], &bf[cur][nt][0]);
            }
        }

        // ---- epilogue: ReLU + store (D fragment layout) ----
        const int g2 = lane >> 2, cq = lane & 3;
        #pragma unroll
        for (int mt = 0; mt < 4; ++mt) {
            const int o0 = wm + mt * 16 + g2;
            #pragma unroll
            for (int nt = 0; nt < 4; ++nt) {
                const int nn0 = half * 64 + wn + nt * 8 + cq * 2;
                float* p = out + (((long)(b * 256 + o0)) * HH + h) * WW + nn0;
                float2 v0, v1;
                v0.x = fmaxf(acc[mt][nt][0], 0.f);
                v0.y = fmaxf(acc[mt][nt][1], 0.f);
                v1.x = fmaxf(acc[mt][nt][2], 0.f);
                v1.y = fmaxf(acc[mt][nt][3], 0.f);
                *(float2*)p = v0;
                *(float2*)(p + 8L * HH * WW) = v1;
            }
        }
    } else {
        // ========== PRODUCERS: 4 warps, all-async staging + dw from smem ==========
        const int pt = t - 256;                   // 0..127
        const int ng = pt & 15, ch = pt >> 4;     // pixel group, channel 0..7
        const int n0 = ng * 4;                    // local pixel base

        // issue A(c) cp.async into its ring stage
        auto issueA = [&](int c) {
            const int s = c % NSTG;
            #pragma unroll
            for (int i = 0; i < 16; ++i) {
                const int idx = pt + i * 128;
                const int m = idx >> 3, q = idx & 7;
                cpa16(sb + AB_OFF + (uint32_t)(s * AB_SZ + m * 144 + q * 16),
                      &g_A_tf32[(c * 256 + m) * 32 + q * 4]);
            }
        };
        // issue X(c) cp.async into 3-deep x ring (zero-filled halo)
        auto issueX = [&](int c) {
            const int xs = c % NSTG;
            #pragma unroll
            for (int i = 0; i < 11; ++i) {
                const int idx = pt + i * 128;          // 0..1295
                if (idx < 1296) {
                    const int q = idx % 18;
                    const int row = (idx / 18) % 9;
                    const int cc = idx / 162;
                    const int gch = c * 8 + cc;
                    const int hh = h + row - 4;
                    const int g0 = half * 64 - 4 + q * 4;
                    const bool ok = ((unsigned)hh < 128u) && (g0 >= 0) && (g0 + 3 < 128);
                    const int hcl = hh < 0 ? 0 : (hh > 127 ? 127 : hh);
                    const int gcl = g0 < 0 ? 0 : (g0 > 124 ? 124 : g0);
                    cpa16z(sb + XB_OFF + (uint32_t)(xs * XB_SZ + (cc * 648 + row * 72 + q * 4) * 4),
                           xb + (long)gch * HH * WW + hcl * WW + gcl, ok ? 16 : 0);
                }
            }
        };

        // prologue: stage 0 in flight
        issueA(0);
        issueX(0);
        asm volatile("cp.async.commit_group;" ::: "memory");

        for (int c = 0; c < NCH; ++c) {
            const int s = c % NSTG;
            // free next A/Y/X stage, then issue next chunk (one group per iter)
            if (c + 1 < NCH) {
                if (c + 1 >= NSTG) bar_sync(BEMPTY((c + 1) % NSTG));
                issueA(c + 1);
                issueX(c + 1);
            }
            asm volatile("cp.async.commit_group;" ::: "memory");
            // wait for the group issued LAST iteration -> own A(c), X(c) slices done
            asm volatile("cp.async.wait_group 1;" ::: "memory");
            // producer-wide barrier: ALL threads' X(c)/A(c) cp.asyncs have landed
            bar_prod();

            // ---- depthwise for chunk c from X smem ----
            const float* Xs = (const float*)(smc + XB_OFF + s * XB_SZ + ch * 2592);
            const float* row4 = Xs + 4 * 72;
            const int gch = c * 8 + ch;
            const float* wp = g_dw + gch * 48;
            uint32_t* Yw = (uint32_t*)(smc + YB_OFF + s * YB_SZ);

            {   // horizontal convs (wh1 -> k=ch, wh2 -> k=8+ch)
                const float4 v0 = *(const float4*)(row4 + n0);
                const float4 v1 = *(const float4*)(row4 + n0 + 4);
                const float4 v2 = *(const float4*)(row4 + n0 + 8);
                float xvv[12] = {v0.x, v0.y, v0.z, v0.w, v1.x, v1.y, v1.z, v1.w,
                                 v2.x, v2.y, v2.z, v2.w};
                float a0 = 0.f, a1 = 0.f, a2 = 0.f, a3 = 0.f;
                float b0 = 0.f, b1 = 0.f, b2 = 0.f, b3 = 0.f;
                #pragma unroll
                for (int k = 0; k < 9; ++k) {
                    const float wa = wp[k], wb2 = wp[12 + k];
                    a0 = fmaf(wa, xvv[k],     a0); b0 = fmaf(wb2, xvv[k],     b0);
                    a1 = fmaf(wa, xvv[k + 1], a1); b1 = fmaf(wb2, xvv[k + 1], b1);
                    a2 = fmaf(wa, xvv[k + 2], a2); b2 = fmaf(wb2, xvv[k + 2], b2);
                    a3 = fmaf(wa, xvv[k + 3], a3); b3 = fmaf(wb2, xvv[k + 3], b3);
                }
                uint4 s0, s1;
                s0.x = f2tf32(a0); s0.y = f2tf32(a1); s0.z = f2tf32(a2); s0.w = f2tf32(a3);
                s1.x = f2tf32(b0); s1.y = f2tf32(b1); s1.z = f2tf32(b2); s1.w = f2tf32(b3);
                *(uint4*)(Yw + (ch)     * 68 + n0) = s0;
                *(uint4*)(Yw + (8 + ch) * 68 + n0) = s1;
            }
            {   // vertical convs (wv1 -> k=16+ch, wv2 -> k=24+ch)
                const float* wq = wp + 24;
                float a0 = 0.f, a1 = 0.f, a2 = 0.f, a3 = 0.f;
                float b0 = 0.f, b1 = 0.f, b2 = 0.f, b3 = 0.f;
                #pragma unroll
                for (int r = 0; r < 9; ++r) {
                    const float4 v = *(const float4*)(Xs + r * 72 + 4 + n0);
                    const float wa = wq[r], wb2 = wq[12 + r];
                    a0 = fmaf(wa, v.x, a0); b0 = fmaf(wb2, v.x, b0);
                    a1 = fmaf(wa, v.y, a1); b1 = fmaf(wb2, v.y, b1);
                    a2 = fmaf(wa, v.z, a2); b2 = fmaf(wb2, v.z, b2);
                    a3 = fmaf(wa, v.w, a3); b3 = fmaf(wb2, v.w, b3);
                }
                uint4 s0, s1;
                s0.x = f2tf32(a0); s0.y = f2tf32(a1); s0.z = f2tf32(a2); s0.w = f2tf32(a3);
                s1.x = f2tf32(b0); s1.y = f2tf32(b1); s1.z = f2tf32(b2); s1.w = f2tf32(b3);
                *(uint4*)(Yw + (16 + ch) * 68 + n0) = s0;
                *(uint4*)(Yw + (24 + ch) * 68 + n0) = s1;
            }

            bar_arrive(BFULL(s));
        }
    }
}

// ================= launch =================
extern "C" void kernel_launch(void* const* d_in, const int* in_sizes, int n_in,
                              void* d_out, int out_size)
{
    const float* x     = (const float*)d_in[0];
    const float* wh1   = (const float*)d_in[1];
    const float* wh2   = (const float*)d_in[2];
    const float* wv1   = (const float*)d_in[3];
    const float* wv2   = (const float*)d_in[4];
    const float* wproj = (const float*)d_in[5];
    float* out = (float*)d_out;

    se_prep<<<1024, 256>>>(wproj, wh1, wh2, wv1, wv2);

    cudaFuncSetAttribute(se_main, cudaFuncAttributeMaxDynamicSharedMemorySize, SMEM_BYTES);
    dim3 grid(2, HH, BB);
    se_main<<<grid, 384, SMEM_BYTES>>>(x, out);
}

// round 16
// speedup vs baseline: 1.3887x; 1.3887x over previous
#include <cuda_runtime.h>
#include <cstdint>

#define HH 128
#define WW 128
#define BB 8
#define NCH 32            // 32 k-chunks; chunk = 8 input channels x 4 branches = 32 y-channels
#define NSTG 4            // pipeline stages

// ---- smem byte layout (per CTA) ----
#define AB_OFF 0                      // 4 x 36864 : A stage [256 m][36 w] (stride 144B)
#define AB_SZ  36864
#define YB_OFF 147456                 // 4 x 8704  : Y stage [32 k][68 w] (stride 272B)
#define YB_SZ  8704
#define SMEM_BYTES 182272

// named barrier ids
#define BFULL(s)  (1 + (s))
#define BEMPTY(s) (5 + (s))

// wproj pre-converted to tf32: [chunk(32)][m(256)][k(32)] u32
__device__ uint32_t g_A_tf32[32 * 256 * 32];
// depthwise weights packed: [ch(256)][conv(4: h1,h2,v1,v2)][12 floats (9 + pad)]
__device__ float g_dw[256 * 4 * 12];

// ================= helpers =================
__device__ __forceinline__ uint32_t smem_u32(const void* p) {
    uint32_t a;
    asm("{ .reg .u64 t; cvta.to.shared.u64 t, %1; cvt.u32.u64 %0, t; }" : "=r"(a) : "l"(p));
    return a;
}
__device__ __forceinline__ void cpa16(uint32_t dst, const void* src) {
    unsigned long long g = (unsigned long long)__cvta_generic_to_global((void*)src);
    asm volatile("cp.async.cg.shared.global [%0], [%1], 16;" :: "r"(dst), "l"(g));
}
__device__ __forceinline__ uint32_t f2tf32(float v) {
    uint32_t u;
    asm("cvt.rna.tf32.f32 %0, %1;" : "=r"(u) : "f"(v));
    return u;
}
__device__ __forceinline__ void ldsm4(uint32_t* r, uint32_t addr) {
    asm volatile("ldmatrix.sync.aligned.m8n8.x4.shared.b16 {%0,%1,%2,%3}, [%4];"
        : "=r"(r[0]), "=r"(r[1]), "=r"(r[2]), "=r"(r[3]) : "r"(addr));
}
__device__ __forceinline__ void mma_tf32(float* d, const uint32_t* a, const uint32_t* b) {
    asm volatile("mma.sync.aligned.m16n8k8.row.col.f32.tf32.tf32.f32 "
        "{%0,%1,%2,%3}, {%4,%5,%6,%7}, {%8,%9}, {%0,%1,%2,%3};"
        : "+f"(d[0]), "+f"(d[1]), "+f"(d[2]), "+f"(d[3])
        : "r"(a[0]), "r"(a[1]), "r"(a[2]), "r"(a[3]), "r"(b[0]), "r"(b[1]));
}
__device__ __forceinline__ void bar_sync(int id) {
    asm volatile("bar.sync %0, 384;" :: "r"(id) : "memory");
}
__device__ __forceinline__ void bar_arrive(int id) {
    asm volatile("bar.arrive %0, 384;" :: "r"(id) : "memory");
}

// ================= prep: wproj -> tf32, dw weights -> packed =================
__global__ void se_prep(const float* __restrict__ wproj,
                        const float* __restrict__ wh1, const float* __restrict__ wh2,
                        const float* __restrict__ wv1, const float* __restrict__ wv2)
{
    int idx = blockIdx.x * 256 + threadIdx.x;   // 262144
    int k = idx & 31;
    int m = (idx >> 5) & 255;
    int c = idx >> 13;
    int br = k >> 3, lc = k & 7;
    float v = wproj[m * 1024 + br * 256 + c * 8 + lc];
    g_A_tf32[(c * 256 + m) * 32 + k] = f2tf32(v);

    if (blockIdx.x == 0) {
        for (int i = threadIdx.x; i < 9216; i += 256) {
            int ch = i / 36, r = i - ch * 36;
            int conv = r / 9, kk = r - conv * 9;
            const float* p = (conv == 0) ? wh1 : (conv == 1) ? wh2 : (conv == 2) ? wv1 : wv2;
            g_dw[(ch * 4 + conv) * 12 + kk] = p[ch * 9 + kk];
        }
    }
}

// ================= main: warp-specialized producer/consumer =================
// grid (2, HH, BB): blockIdx.x = half (N-half of the row)
__global__ __launch_bounds__(384, 1)
void se_main(const float* __restrict__ x, float* __restrict__ out)
{
    extern __shared__ char smc[];
    const uint32_t sb = smem_u32(smc);
    const int half = blockIdx.x, h = blockIdx.y, b = blockIdx.z;
    const int t = threadIdx.x, lane = t & 31;

    const float* xb = x + (long)b * 256 * HH * WW;

    if (t < 256) {
        // ================== CONSUMERS: 8 warps, MMA only ==================
        const int wid = t >> 5;
        const int wm = (wid & 3) * 64;       // M tile base
        const int wn = (wid >> 2) * 32;      // N tile base within 64-px half
        const int fr = lane >> 2, fq = lane & 3;
        const uint32_t aLane = (uint32_t)(((lane & 7) + ((lane >> 3) & 1) * 8) * 144 + ((lane >> 4) << 4));

        float acc[4][4][4];
        #pragma unroll
        for (int i = 0; i < 4; ++i)
            #pragma unroll
            for (int j = 0; j < 4; ++j)
                #pragma unroll
                for (int e = 0; e < 4; ++e) acc[i][j][e] = 0.f;

        uint32_t a[2][4][4];    // double-buffered A fragments
        uint32_t bf[2][4][2];   // double-buffered B fragments

        for (int c = 0; c < NCH; ++c) {
            const int s = c % NSTG;
            bar_sync(BFULL(s));

            const uint32_t abase = sb + AB_OFF + (uint32_t)(s * AB_SZ) + (uint32_t)(wm * 144) + aLane;
            const uint32_t* Yp = (const uint32_t*)(smc + YB_OFF + s * YB_SZ);

            // load kstep 0 fragments
            #pragma unroll
            for (int mt = 0; mt < 4; ++mt)
                ldsm4(a[0][mt], abase + (uint32_t)(mt * 16 * 144));
            #pragma unroll
            for (int nt = 0; nt < 4; ++nt) {
                const int col = wn + nt * 8 + fr;
                bf[0][nt][0] = Yp[fq * 68 + col];
                bf[0][nt][1] = Yp[(fq + 4) * 68 + col];
            }

            #pragma unroll
            for (int ks = 0; ks < 4; ++ks) {
                const int cur = ks & 1, nxt = cur ^ 1;
                if (ks < 3) {        // prefetch next kstep fragments
                    const int k0 = (ks + 1) * 8;
                    #pragma unroll
                    for (int mt = 0; mt < 4; ++mt)
                        ldsm4(a[nxt][mt], abase + (uint32_t)(mt * 16 * 144 + k0 * 4));
                    #pragma unroll
                    for (int nt = 0; nt < 4; ++nt) {
                        const int col = wn + nt * 8 + fr;
                        bf[nxt][nt][0] = Yp[(k0 + fq) * 68 + col];
                        bf[nxt][nt][1] = Yp[(k0 + fq + 4) * 68 + col];
                    }
                    if (ks == 2 && c + NSTG < NCH) bar_arrive(BEMPTY(s));   // all frags in regs
                }
                #pragma unroll
                for (int mt = 0; mt < 4; ++mt)
                    #pragma unroll
                    for (int nt = 0; nt < 4; ++nt)
                        mma_tf32(acc[mt][nt], a[cur][mt], &bf[cur][nt][0]);
            }
        }

        // ---- epilogue: ReLU + store (D fragment layout) ----
        const int g2 = lane >> 2, cq = lane & 3;
        #pragma unroll
        for (int mt = 0; mt < 4; ++mt) {
            const int o0 = wm + mt * 16 + g2;
            #pragma unroll
            for (int nt = 0; nt < 4; ++nt) {
                const int nn0 = half * 64 + wn + nt * 8 + cq * 2;
                float* p = out + (((long)(b * 256 + o0)) * HH + h) * WW + nn0;
                float2 v0, v1;
                v0.x = fmaxf(acc[mt][nt][0], 0.f);
                v0.y = fmaxf(acc[mt][nt][1], 0.f);
                v1.x = fmaxf(acc[mt][nt][2], 0.f);
                v1.y = fmaxf(acc[mt][nt][3], 0.f);
                *(float2*)p = v0;
                *(float2*)(p + 8L * HH * WW) = v1;
            }
        }
    } else {
        // ================== PRODUCERS: 4 warps, dw + A staging ==================
        const int pt = t - 256;                   // 0..127
        const int ng = pt & 15, ch = pt >> 4;     // pixel group, channel 0..7
        const int p0 = half * 64 + ng * 4;        // global pixel base (4 px)
        const int n0 = ng * 4;                    // local pixel base
        const float4 Z4 = make_float4(0.f, 0.f, 0.f, 0.f);

        float4 xh0, xh1, xh2, xv[8];

        auto loadx = [&](int c) {
            const float* xch = xb + (long)(c * 8 + ch) * HH * WW;
            const float* xr = xch + h * WW;
            xh0 = (p0 >= 4)      ? *(const float4*)(xr + p0 - 4) : Z4;
            xh1 =                  *(const float4*)(xr + p0);
            xh2 = (p0 + 7 < 128) ? *(const float4*)(xr + p0 + 4) : Z4;
            #pragma unroll
            for (int r = 0; r < 9; ++r) {
                if (r == 4) continue;
                const int hh = h + r - 4;
                const int i = (r < 4) ? r : r - 1;
                xv[i] = ((unsigned)hh < 128u) ? *(const float4*)(xch + hh * WW + p0) : Z4;
            }
        };

        auto issueA = [&](int c) {
            const int s = c % NSTG;
            #pragma unroll
            for (int i = 0; i < 16; ++i) {
                const int idx = pt + i * 128;
                const int m = idx >> 3, q = idx & 7;
                cpa16(sb + AB_OFF + (uint32_t)(s * AB_SZ + m * 144 + q * 16),
                      &g_A_tf32[(c * 256 + m) * 32 + q * 4]);
            }
        };

        // prologue: A(0) resident before the loop; x(0) in registers
        issueA(0);
        asm volatile("cp.async.commit_group;" ::: "memory");
        asm volatile("cp.async.wait_group 0;" ::: "memory");
        loadx(0);

        for (int c = 0; c < NCH; ++c) {
            const int s = c % NSTG;

            // issue A(c+1) (single BEMPTY wait per stage reuse, at the issue site)
            if (c + 1 < NCH) {
                const int s1 = (c + 1) % NSTG;
                if (c + 1 >= NSTG) bar_sync(BEMPTY(s1));
                issueA(c + 1);
            }
            asm volatile("cp.async.commit_group;" ::: "memory");   // unconditional: uniform accounting

            // ---- depthwise for chunk c from preloaded regs -> Y stage s ----
            const int gch = c * 8 + ch;
            const float* wp = g_dw + gch * 48;
            uint32_t* Yw = (uint32_t*)(smc + YB_OFF + s * YB_SZ);

            {   // horizontal convs (wh1 -> k=ch, wh2 -> k=8+ch)
                float xvv[12];
                xvv[0] = xh0.x; xvv[1] = xh0.y; xvv[2]  = xh0.z; xvv[3]  = xh0.w;
                xvv[4] = xh1.x; xvv[5] = xh1.y; xvv[6]  = xh1.z; xvv[7]  = xh1.w;
                xvv[8] = xh2.x; xvv[9] = xh2.y; xvv[10] = xh2.z; xvv[11] = xh2.w;
                float a0 = 0.f, a1 = 0.f, a2 = 0.f, a3 = 0.f;
                float b0 = 0.f, b1 = 0.f, b2 = 0.f, b3 = 0.f;
                #pragma unroll
                for (int k = 0; k < 9; ++k) {
                    const float wa = wp[k], wb2 = wp[12 + k];
                    a0 = fmaf(wa, xvv[k],     a0); b0 = fmaf(wb2, xvv[k],     b0);
                    a1 = fmaf(wa, xvv[k + 1], a1); b1 = fmaf(wb2, xvv[k + 1], b1);
                    a2 = fmaf(wa, xvv[k + 2], a2); b2 = fmaf(wb2, xvv[k + 2], b2);
                    a3 = fmaf(wa, xvv[k + 3], a3); b3 = fmaf(wb2, xvv[k + 3], b3);
                }
                uint4 s0, s1v;
                s0.x = f2tf32(a0); s0.y = f2tf32(a1); s0.z = f2tf32(a2); s0.w = f2tf32(a3);
                s1v.x = f2tf32(b0); s1v.y = f2tf32(b1); s1v.z = f2tf32(b2); s1v.w = f2tf32(b3);
                *(uint4*)(Yw + (ch)     * 68 + n0) = s0;
                *(uint4*)(Yw + (8 + ch) * 68 + n0) = s1v;
            }
            {   // vertical convs (wv1 -> k=16+ch, wv2 -> k=24+ch)
                const float* wq = wp + 24;
                float a0 = 0.f, a1 = 0.f, a2 = 0.f, a3 = 0.f;
                float b0 = 0.f, b1 = 0.f, b2 = 0.f, b3 = 0.f;
                #pragma unroll
                for (int r = 0; r < 9; ++r) {
                    const float4 v = (r == 4) ? xh1 : xv[(r < 4) ? r : r - 1];
                    const float wa = wq[r], wb2 = wq[12 + r];
                    a0 = fmaf(wa, v.x, a0); b0 = fmaf(wb2, v.x, b0);
                    a1 = fmaf(wa, v.y, a1); b1 = fmaf(wb2, v.y, b1);
                    a2 = fmaf(wa, v.z, a2); b2 = fmaf(wb2, v.z, b2);
                    a3 = fmaf(wa, v.w, a3); b3 = fmaf(wb2, v.w, b3);
                }
                uint4 s0, s1v;
                s0.x = f2tf32(a0); s0.y = f2tf32(a1); s0.z = f2tf32(a2); s0.w = f2tf32(a3);
                s1v.x = f2tf32(b0); s1v.y = f2tf32(b1); s1v.z = f2tf32(b2); s1v.w = f2tf32(b3);
                *(uint4*)(Yw + (16 + ch) * 68 + n0) = s0;
                *(uint4*)(Yw + (24 + ch) * 68 + n0) = s1v;
            }

            // start x loads for next chunk (latency hides under ring slack)
            if (c + 1 < NCH) loadx(c + 1);

            // retire the group committed LAST iteration (contains A(c));
            // A(c+1) stays in flight
            asm volatile("cp.async.wait_group 1;" ::: "memory");
            bar_arrive(BFULL(s));
        }
    }
}

// ================= launch =================
extern "C" void kernel_launch(void* const* d_in, const int* in_sizes, int n_in,
                              void* d_out, int out_size)
{
    const float* x     = (const float*)d_in[0];
    const float* wh1   = (const float*)d_in[1];
    const float* wh2   = (const float*)d_in[2];
    const float* wv1   = (const float*)d_in[3];
    const float* wv2   = (const float*)d_in[4];
    const float* wproj = (const float*)d_in[5];
    float* out = (float*)d_out;

    se_prep<<<1024, 256>>>(wproj, wh1, wh2, wv1, wv2);

    cudaFuncSetAttribute(se_main, cudaFuncAttributeMaxDynamicSharedMemorySize, SMEM_BYTES);
    dim3 grid(2, HH, BB);
    se_main<<<grid, 384, SMEM_BYTES>>>(x, out);
}